// round 7
// baseline (speedup 1.0000x reference)
#include <cuda_runtime.h>
#include <cstdint>

// ---------------- arch-feature detection (proven working) ----------------
#if defined(__CUDA_ARCH__) && (defined(__CUDA_ARCH_FEAT_SM103_ALL) || defined(__CUDA_ARCH_FEAT_SM100_ALL) || defined(__CUDA_ARCH_SPECIFIC__))
#define HAS_TC 1
#else
#define HAS_TC 0
#endif

#define NOISE   128
#define OUTF    512
#define XCOLS   640
#define WCOLS   262656
#define WB_OFF  262144

// chunk space: 2048 main (i0-outer, k-inner) + 16 feat-bias + 4 noise-bias + 1 const
#define CHUNKS  2069
#define SPLITS  74
#define CHPER   28
#define NST     3
#define NTHREADS 288       // warp 0 = MMA warp, warps 1-8 = 256 stagers

#define SM_A(st, mt) (1024u + ((st)*2u + (mt))*16384u)    // 6 x 16KB A tiles
#define SM_B(st)     (99328u + (st)*32768u)               // 3 x 32KB B tiles
#define SMEM_TOTAL   197632
#define SM_FULL(st)  (8u  + (st)*8u)
#define SM_EMPTY(st) (40u + (st)*8u)

// idesc: dtype F32(1)@[4], a/b TF32(2)@[7:9]/[10:12], N=256 -> 32@[17:22], M=128 -> 8@[24:28]
#define IDESC_TF32 ((1u<<4)|(2u<<7)|(2u<<10)|(32u<<17)|(8u<<24))

__device__ float g_scratch[(size_t)SPLITS * 256 * 512];   // split partials (38.8MB)

#if HAS_TC
// ---------------- PTX helpers ----------------
__device__ __forceinline__ uint32_t smem_u32(const void* p){
    uint32_t a;
    asm("{ .reg .u64 t; cvta.to.shared.u64 t, %1; cvt.u32.u64 %0, t; }" : "=r"(a) : "l"(p));
    return a;
}
__device__ __forceinline__ uint32_t sw128(uint32_t o){ return o ^ ((o >> 3) & 0x70u); }
__device__ __forceinline__ uint32_t f2tf32(float f){
    uint32_t r; asm("cvt.rna.tf32.f32 %0, %1;" : "=r"(r) : "f"(f)); return r;
}
__device__ __forceinline__ void sts128(uint32_t addr, uint32_t a, uint32_t b, uint32_t c, uint32_t d){
    asm volatile("st.shared.v4.b32 [%0], {%1,%2,%3,%4};"
                 :: "r"(addr), "r"(a), "r"(b), "r"(c), "r"(d) : "memory");
}
__device__ __forceinline__ bool elect1(){
    uint32_t p;
    asm volatile("{\n\t.reg .pred P;\n\telect.sync _|P, 0xFFFFFFFF;\n\tselp.b32 %0, 1, 0, P;\n\t}" : "=r"(p));
    return p != 0;
}
static constexpr unsigned long long DESC_BASE_SW128 =
    (2ull << 61) | (1ull << 46) | (64ull << 32) | (1ull << 16);
__device__ __forceinline__ uint64_t mkdesc(uint32_t addr){
    return DESC_BASE_SW128 | (uint64_t)((addr >> 4) & 0x3FFFu);
}
__device__ __forceinline__ void mma_tf32(uint32_t d, uint64_t ad, uint64_t bd, uint32_t en){
    asm volatile(
        "{\n\t.reg .pred p;\n\tsetp.ne.u32 p, %4, 0;\n\t"
        "tcgen05.mma.cta_group::1.kind::tf32 [%0], %1, %2, %3, {%5,%5,%5,%5}, p;\n\t}"
        :: "r"(d), "l"(ad), "l"(bd), "r"(IDESC_TF32), "r"(en), "r"(0u) : "memory");
}
#define TMEM_ALLOC(smem_addr, ncols) \
    asm volatile("tcgen05.alloc.cta_group::1.sync.aligned.shared::cta.b32 [%0], %1;" \
                 :: "r"(smem_addr), "r"((uint32_t)(ncols)) : "memory")
#define TMEM_DEALLOC(tmem, ncols) \
    asm volatile("tcgen05.dealloc.cta_group::1.sync.aligned.b32 %0, %1;" :: "r"(tmem), "r"((uint32_t)(ncols)))
#define TMEM_RELINQ() asm volatile("tcgen05.relinquish_alloc_permit.cta_group::1.sync.aligned;")
#define MBAR_INIT(a, n) \
    asm volatile("mbarrier.init.shared.b64 [%0], %1;" :: "r"(a), "r"((uint32_t)(n)) : "memory")
#define MBAR_ARRIVE(a) \
    asm volatile("mbarrier.arrive.shared.b64 _, [%0];" :: "r"(a) : "memory")
#define TC_COMMIT(a) \
    asm volatile("tcgen05.commit.cta_group::1.mbarrier::arrive::one.shared::cluster.b64 [%0];" :: "r"(a) : "memory")
#define FENCE_ASYNC() asm volatile("fence.proxy.async.shared::cta;" ::: "memory")
#define TC_FENCE_AFTER() asm volatile("tcgen05.fence::after_thread_sync;" ::: "memory")
#define TC_WAIT_LD() asm volatile("tcgen05.wait::ld.sync.aligned;" ::: "memory")

__device__ __forceinline__ void mbar_wait(uint32_t mbar, uint32_t parity){
    uint32_t done;
    asm volatile(
        "{\n\t.reg .pred p;\n\t"
        "mbarrier.try_wait.parity.acquire.cta.shared::cta.b64 p, [%1], %2;\n\t"
        "selp.b32 %0, 1, 0, p;\n\t}"
        : "=r"(done) : "r"(mbar), "r"(parity) : "memory");
    if (!done) {
        asm volatile(
            "{\n\t.reg .pred P1;\n\t"
            "WL_%=:\n\t"
            "mbarrier.try_wait.parity.acquire.cta.shared::cta.b64 P1, [%0], %1, 0x989680;\n\t"
            "@P1 bra.uni WD_%=;\n\t"
            "bra.uni WL_%=;\n\t"
            "WD_%=:\n\t}"
            :: "r"(mbar), "r"(parity) : "memory");
    }
}
#define LDTM_X32(r, a) \
    asm volatile("tcgen05.ld.sync.aligned.32x32b.x32.b32 " \
        "{%0,%1,%2,%3,%4,%5,%6,%7,%8,%9,%10,%11,%12,%13,%14,%15," \
        "%16,%17,%18,%19,%20,%21,%22,%23,%24,%25,%26,%27,%28,%29,%30,%31}, [%32];" \
        : "=r"((r)[0]),"=r"((r)[1]),"=r"((r)[2]),"=r"((r)[3]),"=r"((r)[4]),"=r"((r)[5]),"=r"((r)[6]),"=r"((r)[7]), \
          "=r"((r)[8]),"=r"((r)[9]),"=r"((r)[10]),"=r"((r)[11]),"=r"((r)[12]),"=r"((r)[13]),"=r"((r)[14]),"=r"((r)[15]), \
          "=r"((r)[16]),"=r"((r)[17]),"=r"((r)[18]),"=r"((r)[19]),"=r"((r)[20]),"=r"((r)[21]),"=r"((r)[22]),"=r"((r)[23]), \
          "=r"((r)[24]),"=r"((r)[25]),"=r"((r)[26]),"=r"((r)[27]),"=r"((r)[28]),"=r"((r)[29]),"=r"((r)[30]),"=r"((r)[31]) \
        : "r"(a))
#endif // HAS_TC

__global__ __launch_bounds__(NTHREADS, 1)
void hyper_tc(const float* __restrict__ x, const float* __restrict__ W,
              const float* __restrict__ bv)
{
#if HAS_TC
    extern __shared__ char smem[];
    const uint32_t sb  = smem_u32(smem);
    const int tid = threadIdx.x;
    const int wid = tid >> 5;
    const int lid = tid & 31;
    const int nt  = blockIdx.x;              // 0..1 : n-tile
    const int s   = blockIdx.y;              // 0..73: K-split
    const int n0  = nt * 256;
    const int c0  = s * CHPER;
    const int c1  = min(CHUNKS, c0 + CHPER);
    const int nCh = c1 - c0;

    if (wid == 0) TMEM_ALLOC(sb, 512);
    if (tid == 0) {
        #pragma unroll
        for (int st = 0; st < NST; st++) {
            MBAR_INIT(sb + SM_FULL(st), 256);
            MBAR_INIT(sb + SM_EMPTY(st), 1);
        }
    }
    __syncthreads();
    uint32_t tb;
    asm volatile("ld.shared.b32 %0, [%1];" : "=r"(tb) : "r"(sb));

    if (wid == 0) {
        // ================= MMA warp =================
        for (int j = 0; j < nCh; j++) {
            const int st = j % NST;
            mbar_wait(sb + SM_FULL(st), (uint32_t)((j / NST) & 1));
            if (elect1()) {
                uint64_t ad0 = mkdesc(sb + SM_A(st, 0));
                uint64_t ad1 = mkdesc(sb + SM_A(st, 1));
                uint64_t bd  = mkdesc(sb + SM_B(st));
                #pragma unroll
                for (int ks = 0; ks < 4; ks++) {
                    uint32_t en = (j == 0 && ks == 0) ? 0u : 1u;
                    mma_tf32(tb,        ad0 + ks * 2, bd + ks * 2, en);
                    mma_tf32(tb + 256u, ad1 + ks * 2, bd + ks * 2, en);
                }
                TC_COMMIT(sb + SM_EMPTY(st));
            }
        }
    } else {
        // ================= stager threads: u in [0,256) =================
        const int u = tid - 32;
        const float* xg = x + (long)u * XCOLS;
        const uint32_t mt  = (uint32_t)(u >> 7);
        const uint32_t m   = (uint32_t)(u & 127);
        const uint32_t arow = m * 128u;
        const uint32_t brow = (uint32_t)u * 128u;

        float fa[32];
        int   akey_cur = -2;

        // prefetch state (double-buffered in two explicit register arrays)
        float brA[32], brB[32];
        float nvA = 0.f, nvB = 0.f;
        int   keyA = -1, keyB = -1;       // akey (-1 => const-bias chunk)

        // ---- chunk decode + load issue into given buffer ----
        auto prefetch = [&](int c, float (&br)[32], float& nv, int& akey){
            const float* bp; long bstr;
            if (c < 2048) {                      // main: i0-outer, k-inner
                int i0 = (c >> 7) << 5;
                int k  = c & 127;
                bp = W + (long)k * WCOLS + (long)i0 * OUTF + n0 + u; bstr = OUTF;
                nv = xg[k];
                akey = NOISE + i0;
            } else if (c < 2064) {               // feats @ bias-weight
                int i0 = (c - 2048) << 5;
                bp = bv + (long)i0 * OUTF + n0 + u; bstr = OUTF;
                nv = 1.f;
                akey = NOISE + i0;
            } else if (c < 2068) {               // noise @ W-bias
                int k0 = (c - 2064) << 5;
                bp = W + (long)k0 * WCOLS + WB_OFF + n0 + u; bstr = WCOLS;
                nv = 1.f;
                akey = k0;
            } else {                             // const bias
                bp = bv + WB_OFF + n0 + u; bstr = 0;
                nv = 0.f; akey = -1;
            }
            #pragma unroll
            for (int kk = 0; kk < 32; kk++) br[kk] = bp[(long)kk * bstr];
        };

        // ---- stage buffer into smem tiles for pipeline slot j ----
        auto stage = [&](int j, const float (&br)[32], float nv, int akey){
            const int st = j % NST;
            // refresh the feats/noise register cache only when the A-source window moved
            if (akey >= 0 && akey != akey_cur) {
                #pragma unroll
                for (int q = 0; q < 8; q++) {
                    float4 f = *reinterpret_cast<const float4*>(xg + akey + q * 4);
                    fa[q*4+0] = f.x; fa[q*4+1] = f.y; fa[q*4+2] = f.z; fa[q*4+3] = f.w;
                }
                akey_cur = akey;
            }
            if (j >= NST) mbar_wait(sb + SM_EMPTY(st), (uint32_t)(((j / NST) - 1) & 1));
            // B row (8 STS.128)
            {
                uint32_t bb = sb + SM_B(st);
                #pragma unroll
                for (int q = 0; q < 8; q++) {
                    uint32_t off = brow + (uint32_t)q * 16u;
                    sts128(bb + sw128(off),
                           f2tf32(br[q*4+0]), f2tf32(br[q*4+1]),
                           f2tf32(br[q*4+2]), f2tf32(br[q*4+3]));
                }
            }
            // A row (8 STS.128)
            {
                uint32_t ab = sb + SM_A(st, mt);
                #pragma unroll
                for (int q = 0; q < 8; q++) {
                    float v0, v1, v2, v3;
                    if (akey < 0) {
                        v0 = (q == 0) ? 1.f : 0.f; v1 = 0.f; v2 = 0.f; v3 = 0.f;
                    } else {
                        v0 = nv * fa[q*4+0]; v1 = nv * fa[q*4+1];
                        v2 = nv * fa[q*4+2]; v3 = nv * fa[q*4+3];
                    }
                    uint32_t off = arow + (uint32_t)q * 16u;
                    sts128(ab + sw128(off), f2tf32(v0), f2tf32(v1), f2tf32(v2), f2tf32(v3));
                }
            }
            FENCE_ASYNC();
            MBAR_ARRIVE(sb + SM_FULL(st));
        };

        // software-pipelined: loads for chunk j+1 issue before stores of chunk j
        prefetch(c0, brA, nvA, keyA);
        for (int j = 0; j < nCh; j += 2) {
            if (j + 1 < nCh) prefetch(c0 + j + 1, brB, nvB, keyB);
            stage(j, brA, nvA, keyA);
            if (j + 1 < nCh) {
                if (j + 2 < nCh) prefetch(c0 + j + 2, brA, nvA, keyA);
                stage(j + 1, brB, nvB, keyB);
            }
        }
    }

    // ---- all threads wait for final MMA completion ----
    const int jl = nCh - 1;
    mbar_wait(sb + SM_EMPTY(jl % NST), (uint32_t)((jl / NST) & 1));
    TC_FENCE_AFTER();
    __syncthreads();

    // ---- epilogue: warps 0-7 read TMEM, write split partials ----
    if (wid < 8) {
        const int sub = wid & 3;
        const int grp = wid >> 2;
        const int mg  = grp * 128 + sub * 32 + lid;
        float* dst = g_scratch + ((long)s * 256 + mg) * 512 + n0;
        #pragma unroll
        for (int c = 0; c < 8; c++) {
            uint32_t r[32];
            LDTM_X32(r, tb + (uint32_t)grp * 256u + (uint32_t)c * 32u);
            TC_WAIT_LD();
            #pragma unroll
            for (int q = 0; q < 8; q++) {
                *reinterpret_cast<float4*>(dst + c * 32 + q * 4) =
                    make_float4(__uint_as_float(r[q*4+0]), __uint_as_float(r[q*4+1]),
                                __uint_as_float(r[q*4+2]), __uint_as_float(r[q*4+3]));
            }
        }
    }

    __syncthreads();
    if (wid == 0) { TMEM_RELINQ(); TMEM_DEALLOC(tb, 512); }
#endif // HAS_TC
}

// ------- split reduction: 32768 float4 outputs, 4 independent load streams -------
__global__ void reduce_k(float* __restrict__ out)
{
    const int g = blockIdx.x * blockDim.x + threadIdx.x;     // 0..32767 (float4 index)
    const float4* sc = reinterpret_cast<const float4*>(g_scratch);
    float4 a0 = make_float4(0.f,0.f,0.f,0.f), a1 = a0, a2 = a0, a3 = a0;
    #pragma unroll
    for (int t = 0; t < 18; t++) {
        float4 u0 = sc[(size_t)(t)      * 32768 + g];
        float4 u1 = sc[(size_t)(t + 18) * 32768 + g];
        float4 u2 = sc[(size_t)(t + 36) * 32768 + g];
        float4 u3 = sc[(size_t)(t + 54) * 32768 + g];
        a0.x += u0.x; a0.y += u0.y; a0.z += u0.z; a0.w += u0.w;
        a1.x += u1.x; a1.y += u1.y; a1.z += u1.z; a1.w += u1.w;
        a2.x += u2.x; a2.y += u2.y; a2.z += u2.z; a2.w += u2.w;
        a3.x += u3.x; a3.y += u3.y; a3.z += u3.z; a3.w += u3.w;
    }
    {   // tail: splits 72, 73
        float4 u = sc[(size_t)72 * 32768 + g];
        float4 v = sc[(size_t)73 * 32768 + g];
        a0.x += u.x; a0.y += u.y; a0.z += u.z; a0.w += u.w;
        a1.x += v.x; a1.y += v.y; a1.z += v.z; a1.w += v.w;
    }
    reinterpret_cast<float4*>(out)[g] =
        make_float4(a0.x + a1.x + a2.x + a3.x, a0.y + a1.y + a2.y + a3.y,
                    a0.z + a1.z + a2.z + a3.z, a0.w + a1.w + a2.w + a3.w);
}

extern "C" void kernel_launch(void* const* d_in, const int* in_sizes, int n_in,
                              void* d_out, int out_size)
{
    const float* x  = (const float*)d_in[0];   // (256, 640)
    const float* W  = (const float*)d_in[1];   // (128, 262656)
    const float* bv = (const float*)d_in[2];   // (262656,)
    float* out = (float*)d_out;                // (256, 512)

    cudaFuncSetAttribute(hyper_tc, cudaFuncAttributeMaxDynamicSharedMemorySize, SMEM_TOTAL);
    hyper_tc<<<dim3(2, SPLITS), NTHREADS, SMEM_TOTAL>>>(x, W, bv);
    reduce_k<<<256, 128>>>(out);
}

// round 8
// speedup vs baseline: 1.0238x; 1.0238x over previous
#include <cuda_runtime.h>
#include <cstdint>

// ---------------- arch-feature detection (proven working) ----------------
#if defined(__CUDA_ARCH__) && (defined(__CUDA_ARCH_FEAT_SM103_ALL) || defined(__CUDA_ARCH_FEAT_SM100_ALL) || defined(__CUDA_ARCH_SPECIFIC__))
#define HAS_TC 1
#else
#define HAS_TC 0
#endif

#define NOISE   128
#define OUTF    512
#define XCOLS   640
#define WCOLS   262656
#define WB_OFF  262144

// chunk space: 2048 main (i0-outer, k-inner) + 16 feat-bias + 4 noise-bias + 1 const
#define CHUNKS  2069
#define SPLITS  74
#define CHPER   28
#define NST     3
#define NTHREADS 288       // warp 0 = MMA warp, warps 1-8 = 256 stagers

#define SM_A(st, mt) (1024u + ((st)*2u + (mt))*16384u)    // 6 x 16KB A tiles
#define SM_B(st)     (99328u + (st)*32768u)               // 3 x 32KB B tiles
#define SMEM_TOTAL   197632
#define SM_FULL(st)  (8u  + (st)*8u)
#define SM_EMPTY(st) (40u + (st)*8u)

// idesc: dtype F32(1)@[4], a/b TF32(2)@[7:9]/[10:12], N=256 -> 32@[17:22], M=128 -> 8@[24:28]
#define IDESC_TF32 ((1u<<4)|(2u<<7)|(2u<<10)|(32u<<17)|(8u<<24))

__device__ float g_scratch[(size_t)SPLITS * 256 * 512];   // split partials (38.8MB)

#if HAS_TC
// ---------------- PTX helpers ----------------
__device__ __forceinline__ uint32_t smem_u32(const void* p){
    uint32_t a;
    asm("{ .reg .u64 t; cvta.to.shared.u64 t, %1; cvt.u32.u64 %0, t; }" : "=r"(a) : "l"(p));
    return a;
}
__device__ __forceinline__ uint32_t sw128(uint32_t o){ return o ^ ((o >> 3) & 0x70u); }
__device__ __forceinline__ uint32_t f2tf32(float f){
    uint32_t r; asm("cvt.rna.tf32.f32 %0, %1;" : "=r"(r) : "f"(f)); return r;
}
__device__ __forceinline__ void sts128(uint32_t addr, uint32_t a, uint32_t b, uint32_t c, uint32_t d){
    asm volatile("st.shared.v4.b32 [%0], {%1,%2,%3,%4};"
                 :: "r"(addr), "r"(a), "r"(b), "r"(c), "r"(d) : "memory");
}
__device__ __forceinline__ bool elect1(){
    uint32_t p;
    asm volatile("{\n\t.reg .pred P;\n\telect.sync _|P, 0xFFFFFFFF;\n\tselp.b32 %0, 1, 0, P;\n\t}" : "=r"(p));
    return p != 0;
}
static constexpr unsigned long long DESC_BASE_SW128 =
    (2ull << 61) | (1ull << 46) | (64ull << 32) | (1ull << 16);
__device__ __forceinline__ uint64_t mkdesc(uint32_t addr){
    return DESC_BASE_SW128 | (uint64_t)((addr >> 4) & 0x3FFFu);
}
__device__ __forceinline__ void mma_tf32(uint32_t d, uint64_t ad, uint64_t bd, uint32_t en){
    asm volatile(
        "{\n\t.reg .pred p;\n\tsetp.ne.u32 p, %4, 0;\n\t"
        "tcgen05.mma.cta_group::1.kind::tf32 [%0], %1, %2, %3, {%5,%5,%5,%5}, p;\n\t}"
        :: "r"(d), "l"(ad), "l"(bd), "r"(IDESC_TF32), "r"(en), "r"(0u) : "memory");
}
#define TMEM_ALLOC(smem_addr, ncols) \
    asm volatile("tcgen05.alloc.cta_group::1.sync.aligned.shared::cta.b32 [%0], %1;" \
                 :: "r"(smem_addr), "r"((uint32_t)(ncols)) : "memory")
#define TMEM_DEALLOC(tmem, ncols) \
    asm volatile("tcgen05.dealloc.cta_group::1.sync.aligned.b32 %0, %1;" :: "r"(tmem), "r"((uint32_t)(ncols)))
#define TMEM_RELINQ() asm volatile("tcgen05.relinquish_alloc_permit.cta_group::1.sync.aligned;")
#define MBAR_INIT(a, n) \
    asm volatile("mbarrier.init.shared.b64 [%0], %1;" :: "r"(a), "r"((uint32_t)(n)) : "memory")
#define MBAR_ARRIVE(a) \
    asm volatile("mbarrier.arrive.shared.b64 _, [%0];" :: "r"(a) : "memory")
#define TC_COMMIT(a) \
    asm volatile("tcgen05.commit.cta_group::1.mbarrier::arrive::one.shared::cluster.b64 [%0];" :: "r"(a) : "memory")
#define TC_FENCE_BEFORE() asm volatile("tcgen05.fence::before_thread_sync;" ::: "memory")
#define TC_FENCE_AFTER()  asm volatile("tcgen05.fence::after_thread_sync;" ::: "memory")
#define TC_WAIT_LD() asm volatile("tcgen05.wait::ld.sync.aligned;" ::: "memory")

__device__ __forceinline__ void mbar_wait(uint32_t mbar, uint32_t parity){
    uint32_t done;
    asm volatile(
        "{\n\t.reg .pred p;\n\t"
        "mbarrier.try_wait.parity.acquire.cta.shared::cta.b64 p, [%1], %2;\n\t"
        "selp.b32 %0, 1, 0, p;\n\t}"
        : "=r"(done) : "r"(mbar), "r"(parity) : "memory");
    if (!done) {
        asm volatile(
            "{\n\t.reg .pred P1;\n\t"
            "WL_%=:\n\t"
            "mbarrier.try_wait.parity.acquire.cta.shared::cta.b64 P1, [%0], %1, 0x989680;\n\t"
            "@P1 bra.uni WD_%=;\n\t"
            "bra.uni WL_%=;\n\t"
            "WD_%=:\n\t}"
            :: "r"(mbar), "r"(parity) : "memory");
    }
}
#define LDTM_X32(r, a) \
    asm volatile("tcgen05.ld.sync.aligned.32x32b.x32.b32 " \
        "{%0,%1,%2,%3,%4,%5,%6,%7,%8,%9,%10,%11,%12,%13,%14,%15," \
        "%16,%17,%18,%19,%20,%21,%22,%23,%24,%25,%26,%27,%28,%29,%30,%31}, [%32];" \
        : "=r"((r)[0]),"=r"((r)[1]),"=r"((r)[2]),"=r"((r)[3]),"=r"((r)[4]),"=r"((r)[5]),"=r"((r)[6]),"=r"((r)[7]), \
          "=r"((r)[8]),"=r"((r)[9]),"=r"((r)[10]),"=r"((r)[11]),"=r"((r)[12]),"=r"((r)[13]),"=r"((r)[14]),"=r"((r)[15]), \
          "=r"((r)[16]),"=r"((r)[17]),"=r"((r)[18]),"=r"((r)[19]),"=r"((r)[20]),"=r"((r)[21]),"=r"((r)[22]),"=r"((r)[23]), \
          "=r"((r)[24]),"=r"((r)[25]),"=r"((r)[26]),"=r"((r)[27]),"=r"((r)[28]),"=r"((r)[29]),"=r"((r)[30]),"=r"((r)[31]) \
        : "r"(a))
#endif // HAS_TC

__global__ __launch_bounds__(NTHREADS, 1)
void hyper_tc(const float* __restrict__ x, const float* __restrict__ W,
              const float* __restrict__ bv)
{
#if HAS_TC
    extern __shared__ char smem[];
    const uint32_t sb  = smem_u32(smem);
    const int tid = threadIdx.x;
    const int wid = tid >> 5;
    const int lid = tid & 31;
    const int nt  = blockIdx.x;              // 0..1 : n-tile
    const int s   = blockIdx.y;              // 0..73: K-split
    const int n0  = nt * 256;
    const int c0  = s * CHPER;
    const int c1  = min(CHUNKS, c0 + CHPER);
    const int nCh = c1 - c0;

    if (wid == 0) TMEM_ALLOC(sb, 512);
    if (tid == 0) {
        #pragma unroll
        for (int st = 0; st < NST; st++) {
            MBAR_INIT(sb + SM_FULL(st), 256);
            MBAR_INIT(sb + SM_EMPTY(st), 1);
        }
    }
    __syncthreads();
    uint32_t tb;
    asm volatile("ld.shared.b32 %0, [%1];" : "=r"(tb) : "r"(sb));

    if (wid == 0) {
        // ================= MMA warp =================
        for (int j = 0; j < nCh; j++) {
            const int st = j % NST;
            mbar_wait(sb + SM_FULL(st), (uint32_t)((j / NST) & 1));
            TC_FENCE_AFTER();   // order stagers' STS (released by arrive, acquired above) vs MMA reads
            if (elect1()) {
                uint64_t ad0 = mkdesc(sb + SM_A(st, 0));
                uint64_t ad1 = mkdesc(sb + SM_A(st, 1));
                uint64_t bd  = mkdesc(sb + SM_B(st));
                #pragma unroll
                for (int ks = 0; ks < 4; ks++) {
                    uint32_t en = (j == 0 && ks == 0) ? 0u : 1u;
                    mma_tf32(tb,        ad0 + ks * 2, bd + ks * 2, en);
                    mma_tf32(tb + 256u, ad1 + ks * 2, bd + ks * 2, en);
                }
                TC_COMMIT(sb + SM_EMPTY(st));
            }
        }
    } else {
        // ================= stager threads: u in [0,256) =================
        const int u = tid - 32;
        const float* xg = x + (long)u * XCOLS;
        const uint32_t mt  = (uint32_t)(u >> 7);
        const uint32_t m   = (uint32_t)(u & 127);
        const uint32_t arow = m * 128u;
        const uint32_t brow = (uint32_t)u * 128u;

        float fa[32];
        int   akey_cur = -2;

        // prefetch state (double-buffered in two explicit register arrays)
        float brA[32], brB[32];
        float nvA = 0.f, nvB = 0.f;
        int   keyA = -1, keyB = -1;       // akey (-1 => const-bias chunk)

        // ---- chunk decode + load issue into given buffer ----
        auto prefetch = [&](int c, float (&br)[32], float& nv, int& akey){
            const float* bp; long bstr;
            if (c < 2048) {                      // main: i0-outer, k-inner
                int i0 = (c >> 7) << 5;
                int k  = c & 127;
                bp = W + (long)k * WCOLS + (long)i0 * OUTF + n0 + u; bstr = OUTF;
                nv = xg[k];
                akey = NOISE + i0;
            } else if (c < 2064) {               // feats @ bias-weight
                int i0 = (c - 2048) << 5;
                bp = bv + (long)i0 * OUTF + n0 + u; bstr = OUTF;
                nv = 1.f;
                akey = NOISE + i0;
            } else if (c < 2068) {               // noise @ W-bias
                int k0 = (c - 2064) << 5;
                bp = W + (long)k0 * WCOLS + WB_OFF + n0 + u; bstr = WCOLS;
                nv = 1.f;
                akey = k0;
            } else {                             // const bias
                bp = bv + WB_OFF + n0 + u; bstr = 0;
                nv = 0.f; akey = -1;
            }
            #pragma unroll
            for (int kk = 0; kk < 32; kk++) br[kk] = bp[(long)kk * bstr];
        };

        // ---- stage buffer into smem tiles for pipeline slot j ----
        auto stage = [&](int j, const float (&br)[32], float nv, int akey){
            const int st = j % NST;
            // refresh the feats/noise register cache only when the A-source window moved
            if (akey >= 0 && akey != akey_cur) {
                #pragma unroll
                for (int q = 0; q < 8; q++) {
                    float4 f = *reinterpret_cast<const float4*>(xg + akey + q * 4);
                    fa[q*4+0] = f.x; fa[q*4+1] = f.y; fa[q*4+2] = f.z; fa[q*4+3] = f.w;
                }
                akey_cur = akey;
            }
            if (j >= NST) mbar_wait(sb + SM_EMPTY(st), (uint32_t)(((j / NST) - 1) & 1));
            // B row (8 STS.128)
            {
                uint32_t bb = sb + SM_B(st);
                #pragma unroll
                for (int q = 0; q < 8; q++) {
                    uint32_t off = brow + (uint32_t)q * 16u;
                    sts128(bb + sw128(off),
                           f2tf32(br[q*4+0]), f2tf32(br[q*4+1]),
                           f2tf32(br[q*4+2]), f2tf32(br[q*4+3]));
                }
            }
            // A row (8 STS.128)
            {
                uint32_t ab = sb + SM_A(st, mt);
                #pragma unroll
                for (int q = 0; q < 8; q++) {
                    float v0, v1, v2, v3;
                    if (akey < 0) {
                        v0 = (q == 0) ? 1.f : 0.f; v1 = 0.f; v2 = 0.f; v3 = 0.f;
                    } else {
                        v0 = nv * fa[q*4+0]; v1 = nv * fa[q*4+1];
                        v2 = nv * fa[q*4+2]; v3 = nv * fa[q*4+3];
                    }
                    uint32_t off = arow + (uint32_t)q * 16u;
                    sts128(ab + sw128(off), f2tf32(v0), f2tf32(v1), f2tf32(v2), f2tf32(v3));
                }
            }
            // examples-proven ordering: cheap tcgen05 fence + release-arrive
            // (replaces the per-chunk fence.proxy.async STS-drain)
            TC_FENCE_BEFORE();
            MBAR_ARRIVE(sb + SM_FULL(st));
        };

        // software-pipelined: loads for chunk j+1 issue before stores of chunk j
        prefetch(c0, brA, nvA, keyA);
        for (int j = 0; j < nCh; j += 2) {
            if (j + 1 < nCh) prefetch(c0 + j + 1, brB, nvB, keyB);
            stage(j, brA, nvA, keyA);
            if (j + 1 < nCh) {
                if (j + 2 < nCh) prefetch(c0 + j + 2, brA, nvA, keyA);
                stage(j + 1, brB, nvB, keyB);
            }
        }
    }

    // ---- all threads wait for final MMA completion ----
    const int jl = nCh - 1;
    mbar_wait(sb + SM_EMPTY(jl % NST), (uint32_t)((jl / NST) & 1));
    TC_FENCE_AFTER();
    __syncthreads();

    // ---- epilogue: warps 0-7 read TMEM, write split partials ----
    if (wid < 8) {
        const int sub = wid & 3;
        const int grp = wid >> 2;
        const int mg  = grp * 128 + sub * 32 + lid;
        float* dst = g_scratch + ((long)s * 256 + mg) * 512 + n0;
        #pragma unroll
        for (int c = 0; c < 8; c++) {
            uint32_t r[32];
            LDTM_X32(r, tb + (uint32_t)grp * 256u + (uint32_t)c * 32u);
            TC_WAIT_LD();
            #pragma unroll
            for (int q = 0; q < 8; q++) {
                *reinterpret_cast<float4*>(dst + c * 32 + q * 4) =
                    make_float4(__uint_as_float(r[q*4+0]), __uint_as_float(r[q*4+1]),
                                __uint_as_float(r[q*4+2]), __uint_as_float(r[q*4+3]));
            }
        }
    }

    __syncthreads();
    if (wid == 0) { TMEM_RELINQ(); TMEM_DEALLOC(tb, 512); }
#endif // HAS_TC
}

// ------- split reduction: 65536 float2 outputs, 4 independent load streams -------
__global__ void reduce_k(float* __restrict__ out)
{
    const int g = blockIdx.x * blockDim.x + threadIdx.x;     // 0..65535 (float2 index)
    const float2* sc = reinterpret_cast<const float2*>(g_scratch);
    float2 a0 = make_float2(0.f, 0.f), a1 = a0, a2 = a0, a3 = a0;
    #pragma unroll
    for (int t = 0; t < 18; t++) {
        float2 u0 = sc[(size_t)(t)      * 65536 + g];
        float2 u1 = sc[(size_t)(t + 18) * 65536 + g];
        float2 u2 = sc[(size_t)(t + 36) * 65536 + g];
        float2 u3 = sc[(size_t)(t + 54) * 65536 + g];
        a0.x += u0.x; a0.y += u0.y;
        a1.x += u1.x; a1.y += u1.y;
        a2.x += u2.x; a2.y += u2.y;
        a3.x += u3.x; a3.y += u3.y;
    }
    {   // tail: splits 72, 73
        float2 u = sc[(size_t)72 * 65536 + g];
        float2 v = sc[(size_t)73 * 65536 + g];
        a0.x += u.x; a0.y += u.y;
        a1.x += v.x; a1.y += v.y;
    }
    reinterpret_cast<float2*>(out)[g] =
        make_float2(a0.x + a1.x + a2.x + a3.x, a0.y + a1.y + a2.y + a3.y);
}

// profiling-alignment pads: with 4 launches per call, ncu's "-s 5" lands on
// the 2nd replay's hyper_tc instead of always hitting reduce_k.
__global__ void pad_k() {}

extern "C" void kernel_launch(void* const* d_in, const int* in_sizes, int n_in,
                              void* d_out, int out_size)
{
    const float* x  = (const float*)d_in[0];   // (256, 640)
    const float* W  = (const float*)d_in[1];   // (128, 262656)
    const float* bv = (const float*)d_in[2];   // (262656,)
    float* out = (float*)d_out;                // (256, 512)

    cudaFuncSetAttribute(hyper_tc, cudaFuncAttributeMaxDynamicSharedMemorySize, SMEM_TOTAL);
    pad_k<<<1, 32>>>();
    hyper_tc<<<dim3(2, SPLITS), NTHREADS, SMEM_TOTAL>>>(x, W, bv);
    reduce_k<<<512, 128>>>(out);
    pad_k<<<1, 32>>>();
}

// round 9
// speedup vs baseline: 1.0284x; 1.0044x over previous
#include <cuda_runtime.h>
#include <cstdint>

// ---------------- arch-feature detection (proven working) ----------------
#if defined(__CUDA_ARCH__) && (defined(__CUDA_ARCH_FEAT_SM103_ALL) || defined(__CUDA_ARCH_FEAT_SM100_ALL) || defined(__CUDA_ARCH_SPECIFIC__))
#define HAS_TC 1
#else
#define HAS_TC 0
#endif

#define NOISE   128
#define OUTF    512
#define XCOLS   640
#define WCOLS   262656
#define WB_OFF  262144

// chunk space: 2048 main (i0-outer, k-inner) + 16 feat-bias + 4 noise-bias + 1 const
#define CHUNKS  2069
#define SPLITS  74
#define CHPER   28
#define NST     3
#define NTHREADS 288       // warp 0 = MMA warp, warps 1-8 = 256 stagers
#define NCTAS   (2 * SPLITS)               // 148
#define NT_TOTAL (NCTAS * NTHREADS)        // 42624
#define ELEMS2  65536                      // out as float2

#define SM_A(st, mt) (1024u + ((st)*2u + (mt))*16384u)    // 6 x 16KB A tiles
#define SM_B(st)     (99328u + (st)*32768u)               // 3 x 32KB B tiles
#define SMEM_TOTAL   197632
#define SM_FULL(st)  (8u  + (st)*8u)
#define SM_EMPTY(st) (40u + (st)*8u)

// idesc: dtype F32(1)@[4], a/b TF32(2)@[7:9]/[10:12], N=256 -> 32@[17:22], M=128 -> 8@[24:28]
#define IDESC_TF32 ((1u<<4)|(2u<<7)|(2u<<10)|(32u<<17)|(8u<<24))

__device__ float g_scratch[(size_t)SPLITS * 256 * 512];   // split partials (38.8MB)
__device__ unsigned g_bar_cnt = 0;                         // grid barrier state
__device__ volatile unsigned g_bar_sense = 0;              // (self-resetting across replays)

#if HAS_TC
// ---------------- PTX helpers ----------------
__device__ __forceinline__ uint32_t smem_u32(const void* p){
    uint32_t a;
    asm("{ .reg .u64 t; cvta.to.shared.u64 t, %1; cvt.u32.u64 %0, t; }" : "=r"(a) : "l"(p));
    return a;
}
__device__ __forceinline__ uint32_t sw128(uint32_t o){ return o ^ ((o >> 3) & 0x70u); }
__device__ __forceinline__ uint32_t f2tf32(float f){
    uint32_t r; asm("cvt.rna.tf32.f32 %0, %1;" : "=r"(r) : "f"(f)); return r;
}
__device__ __forceinline__ void sts128(uint32_t addr, uint32_t a, uint32_t b, uint32_t c, uint32_t d){
    asm volatile("st.shared.v4.b32 [%0], {%1,%2,%3,%4};"
                 :: "r"(addr), "r"(a), "r"(b), "r"(c), "r"(d) : "memory");
}
__device__ __forceinline__ bool elect1(){
    uint32_t p;
    asm volatile("{\n\t.reg .pred P;\n\telect.sync _|P, 0xFFFFFFFF;\n\tselp.b32 %0, 1, 0, P;\n\t}" : "=r"(p));
    return p != 0;
}
static constexpr unsigned long long DESC_BASE_SW128 =
    (2ull << 61) | (1ull << 46) | (64ull << 32) | (1ull << 16);
__device__ __forceinline__ uint64_t mkdesc(uint32_t addr){
    return DESC_BASE_SW128 | (uint64_t)((addr >> 4) & 0x3FFFu);
}
__device__ __forceinline__ void mma_tf32(uint32_t d, uint64_t ad, uint64_t bd, uint32_t en){
    asm volatile(
        "{\n\t.reg .pred p;\n\tsetp.ne.u32 p, %4, 0;\n\t"
        "tcgen05.mma.cta_group::1.kind::tf32 [%0], %1, %2, %3, {%5,%5,%5,%5}, p;\n\t}"
        :: "r"(d), "l"(ad), "l"(bd), "r"(IDESC_TF32), "r"(en), "r"(0u) : "memory");
}
#define TMEM_ALLOC(smem_addr, ncols) \
    asm volatile("tcgen05.alloc.cta_group::1.sync.aligned.shared::cta.b32 [%0], %1;" \
                 :: "r"(smem_addr), "r"((uint32_t)(ncols)) : "memory")
#define TMEM_DEALLOC(tmem, ncols) \
    asm volatile("tcgen05.dealloc.cta_group::1.sync.aligned.b32 %0, %1;" :: "r"(tmem), "r"((uint32_t)(ncols)))
#define TMEM_RELINQ() asm volatile("tcgen05.relinquish_alloc_permit.cta_group::1.sync.aligned;")
#define MBAR_INIT(a, n) \
    asm volatile("mbarrier.init.shared.b64 [%0], %1;" :: "r"(a), "r"((uint32_t)(n)) : "memory")
#define MBAR_ARRIVE(a) \
    asm volatile("mbarrier.arrive.shared.b64 _, [%0];" :: "r"(a) : "memory")
#define TC_COMMIT(a) \
    asm volatile("tcgen05.commit.cta_group::1.mbarrier::arrive::one.shared::cluster.b64 [%0];" :: "r"(a) : "memory")
#define TC_FENCE_BEFORE() asm volatile("tcgen05.fence::before_thread_sync;" ::: "memory")
#define TC_FENCE_AFTER()  asm volatile("tcgen05.fence::after_thread_sync;" ::: "memory")
#define TC_WAIT_LD() asm volatile("tcgen05.wait::ld.sync.aligned;" ::: "memory")

__device__ __forceinline__ void mbar_wait(uint32_t mbar, uint32_t parity){
    uint32_t done;
    asm volatile(
        "{\n\t.reg .pred p;\n\t"
        "mbarrier.try_wait.parity.acquire.cta.shared::cta.b64 p, [%1], %2;\n\t"
        "selp.b32 %0, 1, 0, p;\n\t}"
        : "=r"(done) : "r"(mbar), "r"(parity) : "memory");
    if (!done) {
        asm volatile(
            "{\n\t.reg .pred P1;\n\t"
            "WL_%=:\n\t"
            "mbarrier.try_wait.parity.acquire.cta.shared::cta.b64 P1, [%0], %1, 0x989680;\n\t"
            "@P1 bra.uni WD_%=;\n\t"
            "bra.uni WL_%=;\n\t"
            "WD_%=:\n\t}"
            :: "r"(mbar), "r"(parity) : "memory");
    }
}
#define LDTM_X32(r, a) \
    asm volatile("tcgen05.ld.sync.aligned.32x32b.x32.b32 " \
        "{%0,%1,%2,%3,%4,%5,%6,%7,%8,%9,%10,%11,%12,%13,%14,%15," \
        "%16,%17,%18,%19,%20,%21,%22,%23,%24,%25,%26,%27,%28,%29,%30,%31}, [%32];" \
        : "=r"((r)[0]),"=r"((r)[1]),"=r"((r)[2]),"=r"((r)[3]),"=r"((r)[4]),"=r"((r)[5]),"=r"((r)[6]),"=r"((r)[7]), \
          "=r"((r)[8]),"=r"((r)[9]),"=r"((r)[10]),"=r"((r)[11]),"=r"((r)[12]),"=r"((r)[13]),"=r"((r)[14]),"=r"((r)[15]), \
          "=r"((r)[16]),"=r"((r)[17]),"=r"((r)[18]),"=r"((r)[19]),"=r"((r)[20]),"=r"((r)[21]),"=r"((r)[22]),"=r"((r)[23]), \
          "=r"((r)[24]),"=r"((r)[25]),"=r"((r)[26]),"=r"((r)[27]),"=r"((r)[28]),"=r"((r)[29]),"=r"((r)[30]),"=r"((r)[31]) \
        : "r"(a))
#endif // HAS_TC

__global__ __launch_bounds__(NTHREADS, 1)
void hyper_tc(const float* __restrict__ x, const float* __restrict__ W,
              const float* __restrict__ bv, float* __restrict__ out)
{
#if HAS_TC
    extern __shared__ char smem[];
    const uint32_t sb  = smem_u32(smem);
    const int tid = threadIdx.x;
    const int wid = tid >> 5;
    const int lid = tid & 31;
    const int nt  = blockIdx.x;              // 0..1 : n-tile
    const int s   = blockIdx.y;              // 0..73: K-split
    const int n0  = nt * 256;
    const int c0  = s * CHPER;
    const int c1  = min(CHUNKS, c0 + CHPER);
    const int nCh = c1 - c0;

    if (wid == 0) TMEM_ALLOC(sb, 512);
    if (tid == 0) {
        #pragma unroll
        for (int st = 0; st < NST; st++) {
            MBAR_INIT(sb + SM_FULL(st), 8);     // 8 per-warp elected arrivals
            MBAR_INIT(sb + SM_EMPTY(st), 1);    // tcgen05.commit
        }
    }
    __syncthreads();
    uint32_t tb;
    asm volatile("ld.shared.b32 %0, [%1];" : "=r"(tb) : "r"(sb));

    if (wid == 0) {
        // ================= MMA warp =================
        for (int j = 0; j < nCh; j++) {
            const int st = j % NST;
            mbar_wait(sb + SM_FULL(st), (uint32_t)((j / NST) & 1));
            TC_FENCE_AFTER();
            if (elect1()) {
                uint64_t ad0 = mkdesc(sb + SM_A(st, 0));
                uint64_t ad1 = mkdesc(sb + SM_A(st, 1));
                uint64_t bd  = mkdesc(sb + SM_B(st));
                #pragma unroll
                for (int ks = 0; ks < 4; ks++) {
                    uint32_t en = (j == 0 && ks == 0) ? 0u : 1u;
                    mma_tf32(tb,        ad0 + ks * 2, bd + ks * 2, en);
                    mma_tf32(tb + 256u, ad1 + ks * 2, bd + ks * 2, en);
                }
                TC_COMMIT(sb + SM_EMPTY(st));
            }
        }
    } else {
        // ================= stager threads: u in [0,256) =================
        const int u = tid - 32;
        const float* xg = x + (long)u * XCOLS;
        const uint32_t mt  = (uint32_t)(u >> 7);
        const uint32_t m   = (uint32_t)(u & 127);
        const uint32_t arow = m * 128u;
        const uint32_t brow = (uint32_t)u * 128u;

        float fa[32];
        int   akey_cur = -2;

        float brA[32], brB[32];
        float nvA = 0.f, nvB = 0.f;
        int   keyA = -1, keyB = -1;

        auto prefetch = [&](int c, float (&br)[32], float& nv, int& akey){
            const float* bp; long bstr;
            if (c < 2048) {                      // main: i0-outer, k-inner
                int i0 = (c >> 7) << 5;
                int k  = c & 127;
                bp = W + (long)k * WCOLS + (long)i0 * OUTF + n0 + u; bstr = OUTF;
                nv = xg[k];
                akey = NOISE + i0;
            } else if (c < 2064) {               // feats @ bias-weight
                int i0 = (c - 2048) << 5;
                bp = bv + (long)i0 * OUTF + n0 + u; bstr = OUTF;
                nv = 1.f;
                akey = NOISE + i0;
            } else if (c < 2068) {               // noise @ W-bias
                int k0 = (c - 2064) << 5;
                bp = W + (long)k0 * WCOLS + WB_OFF + n0 + u; bstr = WCOLS;
                nv = 1.f;
                akey = k0;
            } else {                             // const bias
                bp = bv + WB_OFF + n0 + u; bstr = 0;
                nv = 0.f; akey = -1;
            }
            #pragma unroll
            for (int kk = 0; kk < 32; kk++) br[kk] = bp[(long)kk * bstr];
        };

        auto stage = [&](int j, const float (&br)[32], float nv, int akey){
            const int st = j % NST;
            if (akey >= 0 && akey != akey_cur) {
                #pragma unroll
                for (int q = 0; q < 8; q++) {
                    float4 f = *reinterpret_cast<const float4*>(xg + akey + q * 4);
                    fa[q*4+0] = f.x; fa[q*4+1] = f.y; fa[q*4+2] = f.z; fa[q*4+3] = f.w;
                }
                akey_cur = akey;
            }
            if (j >= NST) mbar_wait(sb + SM_EMPTY(st), (uint32_t)(((j / NST) - 1) & 1));
            // B row (8 STS.128)
            {
                uint32_t bb = sb + SM_B(st);
                #pragma unroll
                for (int q = 0; q < 8; q++) {
                    uint32_t off = brow + (uint32_t)q * 16u;
                    sts128(bb + sw128(off),
                           f2tf32(br[q*4+0]), f2tf32(br[q*4+1]),
                           f2tf32(br[q*4+2]), f2tf32(br[q*4+3]));
                }
            }
            // A row (8 STS.128)
            {
                uint32_t ab = sb + SM_A(st, mt);
                #pragma unroll
                for (int q = 0; q < 8; q++) {
                    float v0, v1, v2, v3;
                    if (akey < 0) {
                        v0 = (q == 0) ? 1.f : 0.f; v1 = 0.f; v2 = 0.f; v3 = 0.f;
                    } else {
                        v0 = nv * fa[q*4+0]; v1 = nv * fa[q*4+1];
                        v2 = nv * fa[q*4+2]; v3 = nv * fa[q*4+3];
                    }
                    uint32_t off = arow + (uint32_t)q * 16u;
                    sts128(ab + sw128(off), f2tf32(v0), f2tf32(v1), f2tf32(v2), f2tf32(v3));
                }
            }
            // per-lane tcgen05 fence, then ONE arrive per warp (FULL count = 8)
            TC_FENCE_BEFORE();
            __syncwarp();
            if (elect1()) MBAR_ARRIVE(sb + SM_FULL(st));
        };

        prefetch(c0, brA, nvA, keyA);
        for (int j = 0; j < nCh; j += 2) {
            if (j + 1 < nCh) prefetch(c0 + j + 1, brB, nvB, keyB);
            stage(j, brA, nvA, keyA);
            if (j + 1 < nCh) {
                if (j + 2 < nCh) prefetch(c0 + j + 2, brA, nvA, keyA);
                stage(j + 1, brB, nvB, keyB);
            }
        }
    }

    // ---- wait for final MMA completion ----
    const int jl = nCh - 1;
    mbar_wait(sb + SM_EMPTY(jl % NST), (uint32_t)((jl / NST) & 1));
    TC_FENCE_AFTER();
    __syncthreads();

    // ---- epilogue: warps 0-7 read TMEM, write split partials ----
    if (wid < 8) {
        const int sub = wid & 3;
        const int grp = wid >> 2;
        const int mg  = grp * 128 + sub * 32 + lid;
        float* dst = g_scratch + ((long)s * 256 + mg) * 512 + n0;
        #pragma unroll
        for (int c = 0; c < 8; c++) {
            uint32_t r[32];
            LDTM_X32(r, tb + (uint32_t)grp * 256u + (uint32_t)c * 32u);
            TC_WAIT_LD();
            #pragma unroll
            for (int q = 0; q < 8; q++) {
                *reinterpret_cast<float4*>(dst + c * 32 + q * 4) =
                    make_float4(__uint_as_float(r[q*4+0]), __uint_as_float(r[q*4+1]),
                                __uint_as_float(r[q*4+2]), __uint_as_float(r[q*4+3]));
            }
        }
    }
    if (wid == 0) { TMEM_RELINQ(); TMEM_DEALLOC(tb, 512); }

    // ---- grid-wide sense-reversing barrier (all 148 CTAs co-resident) ----
    __threadfence();          // make this CTA's scratch stores visible chip-wide
    __syncthreads();
    if (tid == 0) {
        unsigned sv = g_bar_sense;
        unsigned old = atomicAdd(&g_bar_cnt, 1u);
        if (old == (unsigned)(NCTAS - 1)) {
            g_bar_cnt = 0;                    // reset for next replay
            __threadfence();
            g_bar_sense = sv ^ 1u;            // release
        } else {
            while (g_bar_sense == sv) { }     // HW-coalesced L2 spin
        }
    }
    __syncthreads();

    // ---- fused split reduction: 65536 float2 outputs across 42624 threads ----
    {
        const int cta = blockIdx.y * 2 + blockIdx.x;
        const float2* sc = reinterpret_cast<const float2*>(g_scratch);
        for (int e = cta * NTHREADS + tid; e < ELEMS2; e += NT_TOTAL) {
            float2 a0 = make_float2(0.f, 0.f), a1 = a0, a2 = a0, a3 = a0;
            #pragma unroll
            for (int t = 0; t < 18; t++) {
                float2 u0 = sc[(size_t)(t)      * ELEMS2 + e];
                float2 u1 = sc[(size_t)(t + 18) * ELEMS2 + e];
                float2 u2 = sc[(size_t)(t + 36) * ELEMS2 + e];
                float2 u3 = sc[(size_t)(t + 54) * ELEMS2 + e];
                a0.x += u0.x; a0.y += u0.y;
                a1.x += u1.x; a1.y += u1.y;
                a2.x += u2.x; a2.y += u2.y;
                a3.x += u3.x; a3.y += u3.y;
            }
            {   // tail: splits 72, 73
                float2 u = sc[(size_t)72 * ELEMS2 + e];
                float2 v = sc[(size_t)73 * ELEMS2 + e];
                a0.x += u.x; a0.y += u.y;
                a1.x += v.x; a1.y += v.y;
            }
            reinterpret_cast<float2*>(out)[e] =
                make_float2(a0.x + a1.x + a2.x + a3.x, a0.y + a1.y + a2.y + a3.y);
        }
    }
#endif // HAS_TC
}

extern "C" void kernel_launch(void* const* d_in, const int* in_sizes, int n_in,
                              void* d_out, int out_size)
{
    const float* x  = (const float*)d_in[0];   // (256, 640)
    const float* W  = (const float*)d_in[1];   // (128, 262656)
    const float* bv = (const float*)d_in[2];   // (262656,)
    float* out = (float*)d_out;                // (256, 512)

    cudaFuncSetAttribute(hyper_tc, cudaFuncAttributeMaxDynamicSharedMemorySize, SMEM_TOTAL);
    hyper_tc<<<dim3(2, SPLITS), NTHREADS, SMEM_TOTAL>>>(x, W, bv, out);
}

// round 11
// speedup vs baseline: 1.0550x; 1.0259x over previous
#include <cuda_runtime.h>
#include <cstdint>

// ---------------- arch-feature detection (proven working) ----------------
#if defined(__CUDA_ARCH__) && (defined(__CUDA_ARCH_FEAT_SM103_ALL) || defined(__CUDA_ARCH_FEAT_SM100_ALL) || defined(__CUDA_ARCH_SPECIFIC__))
#define HAS_TC 1
#else
#define HAS_TC 0
#endif

#define NOISE   128
#define OUTF    512
#define XCOLS   640
#define WCOLS   262656
#define WB_OFF  262144

// chunk space: 2048 main (i0-outer, k-inner) + 16 feat-bias + 4 noise-bias + 1 const
#define CHUNKS  2069
#define SPLITS  74
#define CHPER   28
#define NST     3
#define NTHREADS 544       // warp 0 = MMA warp, warps 1-16 = 512 stagers
#define NCTAS   (2 * SPLITS)               // 148
#define NT_TOTAL (NCTAS * NTHREADS)
#define ELEMS2  65536                      // out as float2

#define SM_A(st, mt) (1024u + ((st)*2u + (mt))*16384u)    // 6 x 16KB A tiles
#define SM_B(st)     (99328u + (st)*32768u)               // 3 x 32KB B tiles
#define SMEM_TOTAL   197632
#define SM_FULL(st)  (8u  + (st)*8u)
#define SM_EMPTY(st) (40u + (st)*8u)

// idesc: dtype F32(1)@[4], a/b TF32(2)@[7:9]/[10:12], N=256 -> 32@[17:22], M=128 -> 8@[24:28]
#define IDESC_TF32 ((1u<<4)|(2u<<7)|(2u<<10)|(32u<<17)|(8u<<24))

__device__ float g_scratch[(size_t)SPLITS * 256 * 512];   // split partials (38.8MB)
__device__ unsigned g_bar_cnt = 0;                         // grid barrier state
__device__ volatile unsigned g_bar_sense = 0;              // (self-resetting across replays)

#if HAS_TC
// ---------------- PTX helpers ----------------
__device__ __forceinline__ uint32_t smem_u32(const void* p){
    uint32_t a;
    asm("{ .reg .u64 t; cvta.to.shared.u64 t, %1; cvt.u32.u64 %0, t; }" : "=r"(a) : "l"(p));
    return a;
}
__device__ __forceinline__ uint32_t sw128(uint32_t o){ return o ^ ((o >> 3) & 0x70u); }
__device__ __forceinline__ uint32_t f2tf32(float f){
    uint32_t r; asm("cvt.rna.tf32.f32 %0, %1;" : "=r"(r) : "f"(f)); return r;
}
__device__ __forceinline__ void sts128(uint32_t addr, uint32_t a, uint32_t b, uint32_t c, uint32_t d){
    asm volatile("st.shared.v4.b32 [%0], {%1,%2,%3,%4};"
                 :: "r"(addr), "r"(a), "r"(b), "r"(c), "r"(d) : "memory");
}
__device__ __forceinline__ bool elect1(){
    uint32_t p;
    asm volatile("{\n\t.reg .pred P;\n\telect.sync _|P, 0xFFFFFFFF;\n\tselp.b32 %0, 1, 0, P;\n\t}" : "=r"(p));
    return p != 0;
}
static constexpr unsigned long long DESC_BASE_SW128 =
    (2ull << 61) | (1ull << 46) | (64ull << 32) | (1ull << 16);
__device__ __forceinline__ uint64_t mkdesc(uint32_t addr){
    return DESC_BASE_SW128 | (uint64_t)((addr >> 4) & 0x3FFFu);
}
__device__ __forceinline__ void mma_tf32(uint32_t d, uint64_t ad, uint64_t bd, uint32_t en){
    asm volatile(
        "{\n\t.reg .pred p;\n\tsetp.ne.u32 p, %4, 0;\n\t"
        "tcgen05.mma.cta_group::1.kind::tf32 [%0], %1, %2, %3, {%5,%5,%5,%5}, p;\n\t}"
        :: "r"(d), "l"(ad), "l"(bd), "r"(IDESC_TF32), "r"(en), "r"(0u) : "memory");
}
#define TMEM_ALLOC(smem_addr, ncols) \
    asm volatile("tcgen05.alloc.cta_group::1.sync.aligned.shared::cta.b32 [%0], %1;" \
                 :: "r"(smem_addr), "r"((uint32_t)(ncols)) : "memory")
#define TMEM_DEALLOC(tmem, ncols) \
    asm volatile("tcgen05.dealloc.cta_group::1.sync.aligned.b32 %0, %1;" :: "r"(tmem), "r"((uint32_t)(ncols)))
#define TMEM_RELINQ() asm volatile("tcgen05.relinquish_alloc_permit.cta_group::1.sync.aligned;")
#define MBAR_INIT(a, n) \
    asm volatile("mbarrier.init.shared.b64 [%0], %1;" :: "r"(a), "r"((uint32_t)(n)) : "memory")
#define MBAR_ARRIVE(a) \
    asm volatile("mbarrier.arrive.shared.b64 _, [%0];" :: "r"(a) : "memory")
#define TC_COMMIT(a) \
    asm volatile("tcgen05.commit.cta_group::1.mbarrier::arrive::one.shared::cluster.b64 [%0];" :: "r"(a) : "memory")
#define TC_FENCE_BEFORE() asm volatile("tcgen05.fence::before_thread_sync;" ::: "memory")
#define TC_FENCE_AFTER()  asm volatile("tcgen05.fence::after_thread_sync;" ::: "memory")
#define TC_WAIT_LD() asm volatile("tcgen05.wait::ld.sync.aligned;" ::: "memory")

__device__ __forceinline__ void mbar_wait(uint32_t mbar, uint32_t parity){
    uint32_t done;
    asm volatile(
        "{\n\t.reg .pred p;\n\t"
        "mbarrier.try_wait.parity.acquire.cta.shared::cta.b64 p, [%1], %2;\n\t"
        "selp.b32 %0, 1, 0, p;\n\t}"
        : "=r"(done) : "r"(mbar), "r"(parity) : "memory");
    if (!done) {
        asm volatile(
            "{\n\t.reg .pred P1;\n\t"
            "WL_%=:\n\t"
            "mbarrier.try_wait.parity.acquire.cta.shared::cta.b64 P1, [%0], %1, 0x989680;\n\t"
            "@P1 bra.uni WD_%=;\n\t"
            "bra.uni WL_%=;\n\t"
            "WD_%=:\n\t}"
            :: "r"(mbar), "r"(parity) : "memory");
    }
}
#define LDTM_X32(r, a) \
    asm volatile("tcgen05.ld.sync.aligned.32x32b.x32.b32 " \
        "{%0,%1,%2,%3,%4,%5,%6,%7,%8,%9,%10,%11,%12,%13,%14,%15," \
        "%16,%17,%18,%19,%20,%21,%22,%23,%24,%25,%26,%27,%28,%29,%30,%31}, [%32];" \
        : "=r"((r)[0]),"=r"((r)[1]),"=r"((r)[2]),"=r"((r)[3]),"=r"((r)[4]),"=r"((r)[5]),"=r"((r)[6]),"=r"((r)[7]), \
          "=r"((r)[8]),"=r"((r)[9]),"=r"((r)[10]),"=r"((r)[11]),"=r"((r)[12]),"=r"((r)[13]),"=r"((r)[14]),"=r"((r)[15]), \
          "=r"((r)[16]),"=r"((r)[17]),"=r"((r)[18]),"=r"((r)[19]),"=r"((r)[20]),"=r"((r)[21]),"=r"((r)[22]),"=r"((r)[23]), \
          "=r"((r)[24]),"=r"((r)[25]),"=r"((r)[26]),"=r"((r)[27]),"=r"((r)[28]),"=r"((r)[29]),"=r"((r)[30]),"=r"((r)[31]) \
        : "r"(a))
#endif // HAS_TC

__global__ __launch_bounds__(NTHREADS, 1)
void hyper_tc(const float* __restrict__ x, const float* __restrict__ W,
              const float* __restrict__ bv, float* __restrict__ out)
{
#if HAS_TC
    extern __shared__ char smem[];
    const uint32_t sb  = smem_u32(smem);
    const int tid = threadIdx.x;
    const int wid = tid >> 5;
    const int lid = tid & 31;
    const int nt  = blockIdx.x;              // 0..1 : n-tile
    const int s   = blockIdx.y;              // 0..73: K-split
    const int n0  = nt * 256;
    const int c0  = s * CHPER;
    const int c1  = min(CHUNKS, c0 + CHPER);
    const int nCh = c1 - c0;

    if (wid == 0) TMEM_ALLOC(sb, 512);
    if (tid == 0) {
        #pragma unroll
        for (int st = 0; st < NST; st++) {
            MBAR_INIT(sb + SM_FULL(st), 16);    // 16 per-warp elected arrivals
            MBAR_INIT(sb + SM_EMPTY(st), 1);    // tcgen05.commit
        }
    }
    __syncthreads();
    uint32_t tb;
    asm volatile("ld.shared.b32 %0, [%1];" : "=r"(tb) : "r"(sb));

    if (wid == 0) {
        // ================= MMA warp =================
        for (int j = 0; j < nCh; j++) {
            const int st = j % NST;
            mbar_wait(sb + SM_FULL(st), (uint32_t)((j / NST) & 1));
            TC_FENCE_AFTER();
            if (elect1()) {
                uint64_t ad0 = mkdesc(sb + SM_A(st, 0));
                uint64_t ad1 = mkdesc(sb + SM_A(st, 1));
                uint64_t bd  = mkdesc(sb + SM_B(st));
                #pragma unroll
                for (int ks = 0; ks < 4; ks++) {
                    uint32_t en = (j == 0 && ks == 0) ? 0u : 1u;
                    mma_tf32(tb,        ad0 + ks * 2, bd + ks * 2, en);
                    mma_tf32(tb + 256u, ad1 + ks * 2, bd + ks * 2, en);
                }
                TC_COMMIT(sb + SM_EMPTY(st));
            }
        }
    } else {
        // ===== stager threads: u in [0,512): r = u&255 (row), h = u>>8 (kk half) =====
        const int u = tid - 32;
        const int r = u & 255;
        const int h = u >> 8;                    // kk in [h*16, h*16+16)
        const float* xg = x + (long)r * XCOLS;   // batch row r (for A and nv)
        const uint32_t mt  = (uint32_t)(r >> 7);
        const uint32_t m   = (uint32_t)(r & 127);
        const uint32_t colb = (uint32_t)h * 64u;            // byte offset of kk-half in 128B row
        const uint32_t arow = m * 128u + colb;
        const uint32_t brow = (uint32_t)r * 128u + colb;
        const int kh = h * 16;

        float fa[16];
        int   akey_cur = -2;

        float brA[16], brB[16];
        float nvA = 0.f, nvB = 0.f;
        int   keyA = -1, keyB = -1;

        auto prefetch = [&](int c, float (&br)[16], float& nv, int& akey){
            const float* bp; long bstr;
            if (c < 2048) {                      // main: i0-outer, k-inner
                int i0 = (c >> 7) << 5;
                int k  = c & 127;
                bp = W + (long)k * WCOLS + (long)(i0 + kh) * OUTF + n0 + r; bstr = OUTF;
                nv = xg[k];
                akey = NOISE + i0;
            } else if (c < 2064) {               // feats @ bias-weight
                int i0 = (c - 2048) << 5;
                bp = bv + (long)(i0 + kh) * OUTF + n0 + r; bstr = OUTF;
                nv = 1.f;
                akey = NOISE + i0;
            } else if (c < 2068) {               // noise @ W-bias
                int k0 = (c - 2064) << 5;
                bp = W + (long)(k0 + kh) * WCOLS + WB_OFF + n0 + r; bstr = WCOLS;
                nv = 1.f;
                akey = k0;
            } else {                             // const bias
                bp = bv + WB_OFF + n0 + r; bstr = 0;
                nv = 0.f; akey = -1;
            }
            #pragma unroll
            for (int t = 0; t < 16; t++) br[t] = bp[(long)t * bstr];
        };

        auto stage = [&](int j, const float (&br)[16], float nv, int akey){
            const int st = j % NST;
            if (akey >= 0 && akey != akey_cur) {
                #pragma unroll
                for (int q = 0; q < 4; q++) {
                    float4 f = *reinterpret_cast<const float4*>(xg + akey + kh + q * 4);
                    fa[q*4+0] = f.x; fa[q*4+1] = f.y; fa[q*4+2] = f.z; fa[q*4+3] = f.w;
                }
                akey_cur = akey;
            }
            if (j >= NST) mbar_wait(sb + SM_EMPTY(st), (uint32_t)(((j / NST) - 1) & 1));
            // B half-row (4 STS.128)
            {
                uint32_t bb = sb + SM_B(st);
                #pragma unroll
                for (int q = 0; q < 4; q++) {
                    uint32_t off = brow + (uint32_t)q * 16u;
                    sts128(bb + sw128(off),
                           f2tf32(br[q*4+0]), f2tf32(br[q*4+1]),
                           f2tf32(br[q*4+2]), f2tf32(br[q*4+3]));
                }
            }
            // A half-row (4 STS.128)
            {
                uint32_t ab = sb + SM_A(st, mt);
                #pragma unroll
                for (int q = 0; q < 4; q++) {
                    float v0, v1, v2, v3;
                    if (akey < 0) {
                        v0 = (h == 0 && q == 0) ? 1.f : 0.f; v1 = 0.f; v2 = 0.f; v3 = 0.f;
                    } else {
                        v0 = nv * fa[q*4+0]; v1 = nv * fa[q*4+1];
                        v2 = nv * fa[q*4+2]; v3 = nv * fa[q*4+3];
                    }
                    uint32_t off = arow + (uint32_t)q * 16u;
                    sts128(ab + sw128(off), f2tf32(v0), f2tf32(v1), f2tf32(v2), f2tf32(v3));
                }
            }
            TC_FENCE_BEFORE();
            __syncwarp();
            if (elect1()) MBAR_ARRIVE(sb + SM_FULL(st));
        };

        prefetch(c0, brA, nvA, keyA);
        for (int j = 0; j < nCh; j += 2) {
            if (j + 1 < nCh) prefetch(c0 + j + 1, brB, nvB, keyB);
            stage(j, brA, nvA, keyA);
            if (j + 1 < nCh) {
                if (j + 2 < nCh) prefetch(c0 + j + 2, brA, nvA, keyA);
                stage(j + 1, brB, nvB, keyB);
            }
        }
    }

    // ---- wait for final MMA completion ----
    const int jl = nCh - 1;
    mbar_wait(sb + SM_EMPTY(jl % NST), (uint32_t)((jl / NST) & 1));
    TC_FENCE_AFTER();
    __syncthreads();

    // ---- epilogue: warps 0-7 read TMEM, write split partials ----
    if (wid < 8) {
        const int sub = wid & 3;
        const int grp = wid >> 2;
        const int mg  = grp * 128 + sub * 32 + lid;
        float* dst = g_scratch + ((long)s * 256 + mg) * 512 + n0;
        #pragma unroll
        for (int c = 0; c < 8; c++) {
            uint32_t rr[32];
            LDTM_X32(rr, tb + (uint32_t)grp * 256u + (uint32_t)c * 32u);
            TC_WAIT_LD();
            #pragma unroll
            for (int q = 0; q < 8; q++) {
                *reinterpret_cast<float4*>(dst + c * 32 + q * 4) =
                    make_float4(__uint_as_float(rr[q*4+0]), __uint_as_float(rr[q*4+1]),
                                __uint_as_float(rr[q*4+2]), __uint_as_float(rr[q*4+3]));
            }
        }
    }
    if (wid == 0) { TMEM_RELINQ(); TMEM_DEALLOC(tb, 512); }

    // ---- grid-wide sense-reversing barrier (all 148 CTAs co-resident) ----
    __threadfence();
    __syncthreads();
    if (tid == 0) {
        unsigned sv = g_bar_sense;
        unsigned old = atomicAdd(&g_bar_cnt, 1u);
        if (old == (unsigned)(NCTAS - 1)) {
            g_bar_cnt = 0;
            __threadfence();
            g_bar_sense = sv ^ 1u;
        } else {
            while (g_bar_sense == sv) { }
        }
    }
    __syncthreads();

    // ---- fused split reduction: 65536 float2 outputs ----
    {
        const int cta = blockIdx.y * 2 + blockIdx.x;
        const float2* sc = reinterpret_cast<const float2*>(g_scratch);
        for (int e = cta * NTHREADS + tid; e < ELEMS2; e += NT_TOTAL) {
            float2 a0 = make_float2(0.f, 0.f), a1 = a0, a2 = a0, a3 = a0;
            #pragma unroll
            for (int t = 0; t < 18; t++) {
                float2 u0 = sc[(size_t)(t)      * ELEMS2 + e];
                float2 u1 = sc[(size_t)(t + 18) * ELEMS2 + e];
                float2 u2 = sc[(size_t)(t + 36) * ELEMS2 + e];
                float2 u3 = sc[(size_t)(t + 54) * ELEMS2 + e];
                a0.x += u0.x; a0.y += u0.y;
                a1.x += u1.x; a1.y += u1.y;
                a2.x += u2.x; a2.y += u2.y;
                a3.x += u3.x; a3.y += u3.y;
            }
            {
                float2 u = sc[(size_t)72 * ELEMS2 + e];
                float2 v = sc[(size_t)73 * ELEMS2 + e];
                a0.x += u.x; a0.y += u.y;
                a1.x += v.x; a1.y += v.y;
            }
            reinterpret_cast<float2*>(out)[e] =
                make_float2(a0.x + a1.x + a2.x + a3.x, a0.y + a1.y + a2.y + a3.y);
        }
    }
#endif // HAS_TC
}

extern "C" void kernel_launch(void* const* d_in, const int* in_sizes, int n_in,
                              void* d_out, int out_size)
{
    const float* x  = (const float*)d_in[0];   // (256, 640)
    const float* W  = (const float*)d_in[1];   // (128, 262656)
    const float* bv = (const float*)d_in[2];   // (262656,)
    float* out = (float*)d_out;                // (256, 512)

    cudaFuncSetAttribute(hyper_tc, cudaFuncAttributeMaxDynamicSharedMemorySize, SMEM_TOTAL);
    hyper_tc<<<dim3(2, SPLITS), NTHREADS, SMEM_TOTAL>>>(x, W, bv, out);
}